// round 3
// baseline (speedup 1.0000x reference)
#include <cuda_runtime.h>
#include <cuda_bf16.h>
#include <stdint.h>

// Problem constants (fixed by the dataset)
#define B_   8
#define M_   50000
#define D_   256
#define NH_  8
#define GH_  16
#define OUT_ 256
#define SEL_CAP 2048

// ---------------- scratch (device globals; no allocations) ----------------
__device__ __align__(16) float g_S[B_ * M_];
__device__ __align__(16) float g_colsum[B_ * D_];
__device__ float g_kth[B_];
__device__ int   g_selCount[B_];
__device__ int   g_selIdx[B_ * SEL_CAP];
__device__ __align__(16) float g_num[B_ * OUT_];
__device__ float g_den[B_ * NH_];

// ---------------- helpers ----------------
__device__ __forceinline__ unsigned keyOf(float x) {
    unsigned u = __float_as_uint(x);
    return (u & 0x80000000u) ? ~u : (u | 0x80000000u);
}
__device__ __forceinline__ float invKey(unsigned k) {
    unsigned u = (k & 0x80000000u) ? (k & 0x7FFFFFFFu) : ~k;
    return __uint_as_float(u);
}

template<int MASK, int N>
__device__ __forceinline__ void xchg(float* v, int lane) {
    bool up = (lane & MASK) != 0;
#pragma unroll
    for (int i = 0; i < N / 2; i++) {
        float send = up ? v[i] : v[i + N / 2];
        float recv = __shfl_xor_sync(0xFFFFFFFFu, send, MASK);
        float keep = up ? v[i + N / 2] : v[i];
        v[i] = keep + recv;
    }
}

// ---------------- K0: zero scratch (must run every launch: graph replay) ----
__global__ void k0_zero() {
    int i = blockIdx.x * 256 + threadIdx.x;
    if (i < B_ * D_)  g_colsum[i] = 0.f;
    if (i < B_ * OUT_) g_num[i] = 0.f;
    if (i < B_ * NH_)  g_den[i] = 0.f;
    if (i < B_)        g_selCount[i] = 0;
}

// ---------------- K1: gate scores S + column sums of h --------------------
// Block: 128 threads (4 warps). Each warp handles 4 rows/iter.
// Lane owns columns {lane + 32k, k=0..7}.
#define CHUNK 320
__global__ __launch_bounds__(128, 2) void k1_gate(
    const float* __restrict__ h,
    const float* __restrict__ gsl1_w, const float* __restrict__ gsl1_b,
    const float* __restrict__ gsl2_w, const float* __restrict__ gsl2_b)
{
    __shared__ float w1sh[D_ * 20];   // padded stride 20 words -> conflict-free LDS.128
    __shared__ float csum[D_];

    const int tid  = threadIdx.x;
    const int lane = tid & 31;
    const int warp = tid >> 5;
    const int b    = blockIdx.y;

    for (int i = tid; i < D_ * GH_; i += 128) {
        int c = i >> 4, g = i & 15;
        w1sh[c * 20 + g] = gsl1_w[i];
    }
    for (int i = tid; i < D_; i += 128) csum[i] = 0.f;

    // lane -> which gsl-hidden output it ends up owning (bit-reverse of lane&15)
    const int o = ((lane & 1) << 3) | ((lane & 2) << 1) | ((lane & 4) >> 1) | ((lane & 8) >> 3);
    const float g2 = gsl2_w[o];
    const float b1 = gsl1_b[o];
    const float b2 = gsl2_b[0];
    __syncthreads();

    const float* hb = h + (size_t)b * M_ * D_;
    const int base0 = blockIdx.x * CHUNK;

    float colacc[8];
#pragma unroll
    for (int k = 0; k < 8; k++) colacc[k] = 0.f;

    for (int it = 0; it < CHUNK / 16; ++it) {
        const int rbase = base0 + it * 16 + warp * 4;

        float hv[4][8];
#pragma unroll
        for (int r = 0; r < 4; r++) {
            int row = rbase + r;
            if (row < M_) {
                const float* hr = hb + (size_t)row * D_ + lane;
#pragma unroll
                for (int k = 0; k < 8; k++) hv[r][k] = __ldg(hr + k * 32);
            } else {
#pragma unroll
                for (int k = 0; k < 8; k++) hv[r][k] = 0.f;
            }
        }

        float p[4][16];
#pragma unroll
        for (int r = 0; r < 4; r++)
#pragma unroll
            for (int g = 0; g < 16; g++) p[r][g] = 0.f;

#pragma unroll
        for (int k = 0; k < 8; k++) {
            const int c = lane + 32 * k;
            const float* wp = &w1sh[c * 20];
            float4 wa = *(const float4*)(wp);
            float4 wb = *(const float4*)(wp + 4);
            float4 wc = *(const float4*)(wp + 8);
            float4 wd = *(const float4*)(wp + 12);
#pragma unroll
            for (int r = 0; r < 4; r++) {
                float x = hv[r][k];
                p[r][0]  = fmaf(x, wa.x, p[r][0]);
                p[r][1]  = fmaf(x, wa.y, p[r][1]);
                p[r][2]  = fmaf(x, wa.z, p[r][2]);
                p[r][3]  = fmaf(x, wa.w, p[r][3]);
                p[r][4]  = fmaf(x, wb.x, p[r][4]);
                p[r][5]  = fmaf(x, wb.y, p[r][5]);
                p[r][6]  = fmaf(x, wb.z, p[r][6]);
                p[r][7]  = fmaf(x, wb.w, p[r][7]);
                p[r][8]  = fmaf(x, wc.x, p[r][8]);
                p[r][9]  = fmaf(x, wc.y, p[r][9]);
                p[r][10] = fmaf(x, wc.z, p[r][10]);
                p[r][11] = fmaf(x, wc.w, p[r][11]);
                p[r][12] = fmaf(x, wd.x, p[r][12]);
                p[r][13] = fmaf(x, wd.y, p[r][13]);
                p[r][14] = fmaf(x, wd.z, p[r][14]);
                p[r][15] = fmaf(x, wd.w, p[r][15]);
            }
            colacc[k] += (hv[0][k] + hv[1][k]) + (hv[2][k] + hv[3][k]);
        }

        // per-row: reduce 16 partials across warp, then finish gsl2 + sigmoid
        float sv[4];
#pragma unroll
        for (int r = 0; r < 4; r++) {
            float* v = p[r];
            xchg<1, 16>(v, lane);
            xchg<2, 8>(v, lane);
            xchg<4, 4>(v, lane);
            xchg<8, 2>(v, lane);
            v[0] += __shfl_xor_sync(0xFFFFFFFFu, v[0], 16);
            float hid = fmaxf(v[0] + b1, 0.f);
            float contrib = hid * g2;
            contrib += __shfl_xor_sync(0xFFFFFFFFu, contrib, 1);
            contrib += __shfl_xor_sync(0xFFFFFFFFu, contrib, 2);
            contrib += __shfl_xor_sync(0xFFFFFFFFu, contrib, 4);
            contrib += __shfl_xor_sync(0xFFFFFFFFu, contrib, 8);
            float z = contrib + b2;
            sv[r] = 1.0f / (1.0f + expf(-z));
        }
        if (lane == 0 && rbase < M_) {   // M_ % 4 == 0, rbase % 4 == 0
            *(float4*)&g_S[(size_t)b * M_ + rbase] = make_float4(sv[0], sv[1], sv[2], sv[3]);
        }
    }

    // flush column sums
#pragma unroll
    for (int k = 0; k < 8; k++) atomicAdd(&csum[lane + 32 * k], colacc[k]);
    __syncthreads();
    for (int i = tid; i < D_; i += 128) atomicAdd(&g_colsum[b * D_ + i], csum[i]);
}

// ---------------- K2: exact k-th largest of S per batch (radix select) ----
// NOTE: histogram loop uses a UNIFORM trip count per block (padded, predicated)
// so __ballot_sync never executes under ragged warp divergence (round-2 hang).
__global__ __launch_bounds__(1024) void k2_select(const int* __restrict__ kptr) {
    const int b = blockIdx.x;
    __shared__ unsigned hist[256];
    __shared__ unsigned sh_prefix;
    __shared__ int sh_kneed;

    int kk = kptr ? *kptr : 500;
    if (kk <= 0 || kk > M_) {
        float kf = __int_as_float(kk);
        if (kf >= 1.f && kf <= (float)M_) kk = (int)kf;
        else kk = kk < 1 ? 1 : M_;
    }
    if (kk > M_) kk = M_;

    if (threadIdx.x == 0) { sh_prefix = 0u; sh_kneed = kk; }
    __syncthreads();

    const float* Sb = &g_S[(size_t)b * M_];
    const int NT = 1024;
    const int ITERS = (M_ + NT - 1) / NT;   // uniform for the whole block

    for (int pass = 3; pass >= 0; --pass) {
        for (int i = threadIdx.x; i < 256; i += NT) hist[i] = 0u;
        __syncthreads();
        const unsigned pre = sh_prefix;
        const int shift = pass * 8;
        const unsigned himask = (pass == 3) ? 0u : (0xFFFFFFFFu << (shift + 8));

        for (int it = 0; it < ITERS; ++it) {
            const int i = it * NT + threadIdx.x;
            const bool inb = (i < M_);
            unsigned key = inb ? keyOf(Sb[i]) : 0u;
            bool part = inb && (((key ^ pre) & himask) == 0u);
            unsigned act = __ballot_sync(0xFFFFFFFFu, part);
            if (part) {
                int bin = (key >> shift) & 255;
                unsigned peers = __match_any_sync(act, bin);
                int leader = __ffs(peers) - 1;
                if ((int)(threadIdx.x & 31) == leader)
                    atomicAdd(&hist[bin], (unsigned)__popc(peers));
            }
        }
        __syncthreads();
        if (threadIdx.x == 0) {
            int need = sh_kneed;
            unsigned cum = 0; int bin = 0;
            for (int v = 255; v >= 0; --v) {
                if (cum + hist[v] >= (unsigned)need) { bin = v; break; }
                cum += hist[v];
            }
            sh_prefix = pre | ((unsigned)bin << shift);
            sh_kneed = need - (int)cum;
        }
        __syncthreads();
    }
    if (threadIdx.x == 0) g_kth[b] = invKey(sh_prefix);
}

// ---------------- K3: mask output + gather selected indices ---------------
__global__ void k3_mask(float* __restrict__ outmask) {
    const int b = blockIdx.y;
    const int m = blockIdx.x * 256 + threadIdx.x;
    if (m >= M_) return;
    const int idx = b * M_ + m;
    float s = g_S[idx];
    bool sel = s >= g_kth[b];
    outmask[idx] = sel ? 1.f : 0.f;
    if (sel) {
        int pos = atomicAdd(&g_selCount[b], 1);
        if (pos < SEL_CAP) g_selIdx[b * SEL_CAP + pos] = m;
    }
}

// ---------------- K4: selected-row correction (num / den) -----------------
#define RS 16
__global__ __launch_bounds__(256) void k4_selected(
    const float* __restrict__ h,
    const float* __restrict__ att_w, const float* __restrict__ att_b,
    const float* __restrict__ w_w)
{
    __shared__ float hsh[RS][D_];
    __shared__ float efac[RS][NH_];
    __shared__ float aw[D_ * NH_];

    const int b = blockIdx.y;
    const int tid = threadIdx.x;
    for (int i = tid; i < D_ * NH_; i += 256) aw[i] = att_w[i];

    int cnt = g_selCount[b];
    if (cnt > SEL_CAP) cnt = SEL_CAP;
    const int ngroups = (cnt + RS - 1) / RS;
    const float* hb = h + (size_t)b * M_ * D_;

    for (int g = blockIdx.x; g < ngroups; g += gridDim.x) {
        __syncthreads();
        for (int i = tid; i < RS * D_; i += 256) {
            int r = i >> 8, c = i & 255;
            int si = g * RS + r;
            hsh[r][c] = (si < cnt) ? hb[(size_t)g_selIdx[b * SEL_CAP + si] * D_ + c] : 0.f;
        }
        __syncthreads();
        if (tid < RS * NH_) {
            int r = tid >> 3, hd = tid & 7;
            float s = 0.f;
            for (int c = 0; c < D_; c++) s = fmaf(hsh[r][c], aw[c * NH_ + hd], s);
            float a = fmaxf(s + att_b[hd], 0.f);
            efac[r][hd] = (g * RS + r < cnt) ? (expf(a) - 1.f) : 0.f;
        }
        __syncthreads();

        const int e = tid;
        float acc[RS];
#pragma unroll
        for (int r = 0; r < RS; r++) acc[r] = 0.f;
        for (int c = 0; c < D_; c++) {
            float w = __ldg(&w_w[c * OUT_ + e]);
#pragma unroll
            for (int r = 0; r < RS; r++) acc[r] = fmaf(hsh[r][c], w, acc[r]);
        }
        const int hd = e >> 5;
        float s = 0.f;
#pragma unroll
        for (int r = 0; r < RS; r++) s = fmaf(efac[r][hd], acc[r], s);
        atomicAdd(&g_num[b * OUT_ + e], s);
        if (tid < NH_) {
            float d = 0.f;
#pragma unroll
            for (int r = 0; r < RS; r++) d += efac[r][tid];
            atomicAdd(&g_den[b * NH_ + tid], d);
        }
    }
}

// ---------------- K5: base term + Q_res + combine + normalize -------------
__global__ __launch_bounds__(256) void k5_final(
    const float* __restrict__ w_w,
    const float* __restrict__ res_w, const float* __restrict__ res_b,
    float* __restrict__ out)
{
    const int b = blockIdx.x;
    const int e = threadIdx.x;
    __shared__ float cs[D_];
    __shared__ float red[256];

    cs[e] = g_colsum[b * D_ + e];
    __syncthreads();

    float base = 0.f, qr = 0.f;
#pragma unroll 4
    for (int c = 0; c < D_; c++) {
        float x = cs[c];
        base = fmaf(x, __ldg(&w_w[c * OUT_ + e]), base);
        qr   = fmaf(x, __ldg(&res_w[c * OUT_ + e]), qr);
    }
    qr *= (1.0f / (float)M_);
    float Qres = fmaxf(qr + res_b[e], 0.f);
    float den = (float)M_ + g_den[b * NH_ + (e >> 5)];
    float ov = (base + g_num[b * OUT_ + e]) / den;
    float v = fmaxf(ov + Qres, 0.f);

    // mean
    red[e] = v; __syncthreads();
    for (int s = 128; s > 0; s >>= 1) {
        if (e < s) red[e] += red[e + s];
        __syncthreads();
    }
    float mean = red[0] * (1.0f / 256.0f);
    __syncthreads();
    float dm = v - mean;
    red[e] = dm * dm; __syncthreads();
    for (int s = 128; s > 0; s >>= 1) {
        if (e < s) red[e] += red[e + s];
        __syncthreads();
    }
    float var = red[0] * (1.0f / 256.0f);
    out[b * OUT_ + e] = dm * rsqrtf(var + 1e-8f);
}

// ---------------- launch -----------------
extern "C" void kernel_launch(void* const* d_in, const int* in_sizes, int n_in,
                              void* d_out, int out_size)
{
    const float* h      = (const float*)d_in[0];
    const float* att_w  = (const float*)d_in[1];
    const float* att_b  = (const float*)d_in[2];
    const float* w_w    = (const float*)d_in[3];
    const float* res_w  = (const float*)d_in[4];
    const float* res_b  = (const float*)d_in[5];
    const float* gsl1_w = (const float*)d_in[6];
    const float* gsl1_b = (const float*)d_in[7];
    const float* gsl2_w = (const float*)d_in[8];
    const float* gsl2_b = (const float*)d_in[9];
    const int*   kptr   = (n_in > 10) ? (const int*)d_in[10] : nullptr;

    float* out  = (float*)d_out;              // [B, 1, OUT] -> 2048 floats
    float* mask = out + B_ * OUT_;            // [B, 1, M]   -> 400000 floats

    k0_zero<<<8, 256>>>();
    {
        dim3 grid((M_ + CHUNK - 1) / CHUNK, B_);
        k1_gate<<<grid, 128>>>(h, gsl1_w, gsl1_b, gsl2_w, gsl2_b);
    }
    k2_select<<<B_, 1024>>>(kptr);
    {
        dim3 grid((M_ + 255) / 256, B_);
        k3_mask<<<grid, 256>>>(mask);
    }
    {
        dim3 grid(16, B_);
        k4_selected<<<grid, 256>>>(h, att_w, att_b, w_w);
    }
    k5_final<<<B_, 256>>>(w_w, res_w, res_b, out);
}

// round 4
// speedup vs baseline: 1.0458x; 1.0458x over previous
#include <cuda_runtime.h>
#include <cuda_bf16.h>
#include <stdint.h>

// Problem constants (fixed by the dataset)
#define B_   8
#define M_   50000
#define D_   256
#define NH_  8
#define GH_  16
#define OUT_ 256
#define SEL_CAP 2048

// ---------------- scratch (device globals; no allocations) ----------------
__device__ __align__(16) float g_S[B_ * M_];
__device__ __align__(16) float g_colsum[B_ * D_];
__device__ float g_kth[B_];
__device__ int   g_selCount[B_];
__device__ int   g_selIdx[B_ * SEL_CAP];
__device__ __align__(16) float g_num[B_ * OUT_];
__device__ float g_den[B_ * NH_];

// ---------------- helpers ----------------
__device__ __forceinline__ unsigned keyOf(float x) {
    unsigned u = __float_as_uint(x);
    return (u & 0x80000000u) ? ~u : (u | 0x80000000u);
}
__device__ __forceinline__ float invKey(unsigned k) {
    unsigned u = (k & 0x80000000u) ? (k & 0x7FFFFFFFu) : ~k;
    return __uint_as_float(u);
}

// f32x2 packed ops (Blackwell sm_103a)
__device__ __forceinline__ unsigned long long f32x2add(unsigned long long a, unsigned long long b) {
    unsigned long long r;
    asm("add.rn.f32x2 %0, %1, %2;" : "=l"(r) : "l"(a), "l"(b));
    return r;
}
#define FMA2(acc, a, b) asm("fma.rn.f32x2 %0, %1, %2, %0;" : "+l"(acc) : "l"(a), "l"(b))

__device__ __forceinline__ unsigned long long packdup(float x) {
    unsigned long long r;
    unsigned xu = __float_as_uint(x);
    asm("mov.b64 %0, {%1, %1};" : "=l"(r) : "r"(xu));
    return r;
}

template<int MASK, int N>
__device__ __forceinline__ void xchg64(unsigned long long* v, int lane) {
    bool up = (lane & MASK) != 0;
#pragma unroll
    for (int i = 0; i < N / 2; i++) {
        unsigned long long send = up ? v[i] : v[i + N / 2];
        unsigned long long recv = __shfl_xor_sync(0xFFFFFFFFu, send, MASK);
        unsigned long long keep = up ? v[i + N / 2] : v[i];
        v[i] = f32x2add(keep, recv);
    }
}

// ---------------- K0: zero scratch (must run every launch: graph replay) ----
__global__ void k0_zero() {
    int i = blockIdx.x * 256 + threadIdx.x;
    if (i < B_ * D_)  g_colsum[i] = 0.f;
    if (i < B_ * OUT_) g_num[i] = 0.f;
    if (i < B_ * NH_)  g_den[i] = 0.f;
    if (i < B_)        g_selCount[i] = 0;
}

// ---------------- K1: gate scores S + column sums of h --------------------
// Block: 128 threads (4 warps). Each warp handles 4 rows/iter.
// Lane owns columns {lane + 32k, k=0..7}. Hidden units packed in f32x2 pairs:
// slot p (p=0..7) accumulates hidden units (2p, 2p+1) via fma.rn.f32x2.
// Weights in smem as u64 pairs, column stride 10 u64 = 20 words ->
// lane*20 mod 32 covers all 8 disjoint 4-bank regions: conflict-free LDS.128.
#define CHUNK 912   // 57 groups of 16 rows; 55 blocks/batch * 8 = 440 blocks = 1 wave @3/SM
__global__ __launch_bounds__(128, 3) void k1_gate(
    const float* __restrict__ h,
    const float* __restrict__ gsl1_w, const float* __restrict__ gsl1_b,
    const float* __restrict__ gsl2_w, const float* __restrict__ gsl2_b)
{
    __shared__ unsigned long long w1sh[D_ * 10];  // 8 pairs + 2 pad per column
    __shared__ float csum[D_];

    const int tid  = threadIdx.x;
    const int lane = tid & 31;
    const int warp = tid >> 5;
    const int b    = blockIdx.y;

    // fill packed weights: w1sh[c*10 + p] = (gsl1_w[c*16+2p], gsl1_w[c*16+2p+1])
    for (int i = tid; i < D_ * 8; i += 128) {
        int c = i >> 3, p = i & 7;
        unsigned lo = __float_as_uint(gsl1_w[c * GH_ + 2 * p]);
        unsigned hi = __float_as_uint(gsl1_w[c * GH_ + 2 * p + 1]);
        w1sh[c * 10 + p] = (unsigned long long)lo | ((unsigned long long)hi << 32);
    }
    for (int i = tid; i < D_; i += 128) csum[i] = 0.f;

    // lane -> slot s it ends up owning after the butterfly: s = bitrev3(lane&7)
    const int s = ((lane & 1) << 2) | (lane & 2) | ((lane & 4) >> 2);
    const float w2lo = gsl2_w[2 * s];
    const float w2hi = gsl2_w[2 * s + 1];
    const float b1lo = gsl1_b[2 * s];
    const float b1hi = gsl1_b[2 * s + 1];
    const float b2 = gsl2_b[0];
    __syncthreads();

    const float* hb = h + (size_t)b * M_ * D_;
    const int base0 = blockIdx.x * CHUNK;

    float colacc[8];
#pragma unroll
    for (int k = 0; k < 8; k++) colacc[k] = 0.f;

    for (int it = 0; it < CHUNK / 16; ++it) {
        if (base0 + it * 16 >= M_) break;          // M_ % 16 == 0: groups are all-or-nothing
        const int rbase = base0 + it * 16 + warp * 4;

        float hv[4][8];
#pragma unroll
        for (int r = 0; r < 4; r++) {
            const float* hr = hb + (size_t)(rbase + r) * D_ + lane;
#pragma unroll
            for (int k = 0; k < 8; k++) hv[r][k] = __ldg(hr + k * 32);
        }

        unsigned long long p2[4][8];
#pragma unroll
        for (int r = 0; r < 4; r++)
#pragma unroll
            for (int p = 0; p < 8; p++) p2[r][p] = 0ULL;

#pragma unroll
        for (int k = 0; k < 8; k++) {
            const int c = lane + 32 * k;
            const unsigned long long* wp = &w1sh[c * 10];
            ulonglong2 w01 = *(const ulonglong2*)(wp);
            ulonglong2 w23 = *(const ulonglong2*)(wp + 2);
            ulonglong2 w45 = *(const ulonglong2*)(wp + 4);
            ulonglong2 w67 = *(const ulonglong2*)(wp + 6);
#pragma unroll
            for (int r = 0; r < 4; r++) {
                unsigned long long xx = packdup(hv[r][k]);
                FMA2(p2[r][0], xx, w01.x);
                FMA2(p2[r][1], xx, w01.y);
                FMA2(p2[r][2], xx, w23.x);
                FMA2(p2[r][3], xx, w23.y);
                FMA2(p2[r][4], xx, w45.x);
                FMA2(p2[r][5], xx, w45.y);
                FMA2(p2[r][6], xx, w67.x);
                FMA2(p2[r][7], xx, w67.y);
            }
            colacc[k] += (hv[0][k] + hv[1][k]) + (hv[2][k] + hv[3][k]);
        }

        // per-row: butterfly-reduce 8 f32x2 slots across warp, finish gsl2+sigmoid
        float sv[4];
#pragma unroll
        for (int r = 0; r < 4; r++) {
            unsigned long long* v = p2[r];
            xchg64<1, 8>(v, lane);
            xchg64<2, 4>(v, lane);
            xchg64<4, 2>(v, lane);
            v[0] = f32x2add(v[0], __shfl_xor_sync(0xFFFFFFFFu, v[0], 8));
            v[0] = f32x2add(v[0], __shfl_xor_sync(0xFFFFFFFFu, v[0], 16));
            float lo = __uint_as_float((unsigned)(v[0] & 0xFFFFFFFFu));
            float hi = __uint_as_float((unsigned)(v[0] >> 32));
            float h0 = fmaxf(lo + b1lo, 0.f);
            float h1 = fmaxf(hi + b1hi, 0.f);
            float contrib = fmaf(h0, w2lo, h1 * w2hi);
            contrib += __shfl_xor_sync(0xFFFFFFFFu, contrib, 1);
            contrib += __shfl_xor_sync(0xFFFFFFFFu, contrib, 2);
            contrib += __shfl_xor_sync(0xFFFFFFFFu, contrib, 4);
            float z = contrib + b2;
            sv[r] = 1.0f / (1.0f + expf(-z));
        }
        if (lane == 0) {
            *(float4*)&g_S[(size_t)b * M_ + rbase] = make_float4(sv[0], sv[1], sv[2], sv[3]);
        }
    }

    // flush column sums
#pragma unroll
    for (int k = 0; k < 8; k++) atomicAdd(&csum[lane + 32 * k], colacc[k]);
    __syncthreads();
    for (int i = tid; i < D_; i += 128) atomicAdd(&g_colsum[b * D_ + i], csum[i]);
}

// ---------------- K2: exact k-th largest of S per batch (radix select) ----
// Uniform trip count per block so __ballot_sync never runs under ragged divergence.
__global__ __launch_bounds__(1024) void k2_select(const int* __restrict__ kptr) {
    const int b = blockIdx.x;
    __shared__ unsigned hist[256];
    __shared__ unsigned sh_prefix;
    __shared__ int sh_kneed;

    int kk = kptr ? *kptr : 500;
    if (kk <= 0 || kk > M_) {
        float kf = __int_as_float(kk);
        if (kf >= 1.f && kf <= (float)M_) kk = (int)kf;
        else kk = kk < 1 ? 1 : M_;
    }
    if (kk > M_) kk = M_;

    if (threadIdx.x == 0) { sh_prefix = 0u; sh_kneed = kk; }
    __syncthreads();

    const float* Sb = &g_S[(size_t)b * M_];
    const int NT = 1024;
    const int ITERS = (M_ + NT - 1) / NT;

    for (int pass = 3; pass >= 0; --pass) {
        for (int i = threadIdx.x; i < 256; i += NT) hist[i] = 0u;
        __syncthreads();
        const unsigned pre = sh_prefix;
        const int shift = pass * 8;
        const unsigned himask = (pass == 3) ? 0u : (0xFFFFFFFFu << (shift + 8));

        for (int it = 0; it < ITERS; ++it) {
            const int i = it * NT + threadIdx.x;
            const bool inb = (i < M_);
            unsigned key = inb ? keyOf(Sb[i]) : 0u;
            bool part = inb && (((key ^ pre) & himask) == 0u);
            unsigned act = __ballot_sync(0xFFFFFFFFu, part);
            if (part) {
                int bin = (key >> shift) & 255;
                unsigned peers = __match_any_sync(act, bin);
                int leader = __ffs(peers) - 1;
                if ((int)(threadIdx.x & 31) == leader)
                    atomicAdd(&hist[bin], (unsigned)__popc(peers));
            }
        }
        __syncthreads();
        if (threadIdx.x == 0) {
            int need = sh_kneed;
            unsigned cum = 0; int bin = 0;
            for (int v = 255; v >= 0; --v) {
                if (cum + hist[v] >= (unsigned)need) { bin = v; break; }
                cum += hist[v];
            }
            sh_prefix = pre | ((unsigned)bin << shift);
            sh_kneed = need - (int)cum;
        }
        __syncthreads();
    }
    if (threadIdx.x == 0) g_kth[b] = invKey(sh_prefix);
}

// ---------------- K3: mask output + gather selected indices ---------------
__global__ void k3_mask(float* __restrict__ outmask) {
    const int b = blockIdx.y;
    const int m = blockIdx.x * 256 + threadIdx.x;
    if (m >= M_) return;
    const int idx = b * M_ + m;
    float s = g_S[idx];
    bool sel = s >= g_kth[b];
    outmask[idx] = sel ? 1.f : 0.f;
    if (sel) {
        int pos = atomicAdd(&g_selCount[b], 1);
        if (pos < SEL_CAP) g_selIdx[b * SEL_CAP + pos] = m;
    }
}

// ---------------- K4: selected-row correction (num / den) -----------------
#define RS 16
__global__ __launch_bounds__(256) void k4_selected(
    const float* __restrict__ h,
    const float* __restrict__ att_w, const float* __restrict__ att_b,
    const float* __restrict__ w_w)
{
    __shared__ float hsh[RS][D_];
    __shared__ float efac[RS][NH_];
    __shared__ float aw[D_ * NH_];

    const int b = blockIdx.y;
    const int tid = threadIdx.x;
    for (int i = tid; i < D_ * NH_; i += 256) aw[i] = att_w[i];

    int cnt = g_selCount[b];
    if (cnt > SEL_CAP) cnt = SEL_CAP;
    const int ngroups = (cnt + RS - 1) / RS;
    const float* hb = h + (size_t)b * M_ * D_;

    for (int g = blockIdx.x; g < ngroups; g += gridDim.x) {
        __syncthreads();
        for (int i = tid; i < RS * D_; i += 256) {
            int r = i >> 8, c = i & 255;
            int si = g * RS + r;
            hsh[r][c] = (si < cnt) ? hb[(size_t)g_selIdx[b * SEL_CAP + si] * D_ + c] : 0.f;
        }
        __syncthreads();
        if (tid < RS * NH_) {
            int r = tid >> 3, hd = tid & 7;
            float s = 0.f;
            for (int c = 0; c < D_; c++) s = fmaf(hsh[r][c], aw[c * NH_ + hd], s);
            float a = fmaxf(s + att_b[hd], 0.f);
            efac[r][hd] = (g * RS + r < cnt) ? (expf(a) - 1.f) : 0.f;
        }
        __syncthreads();

        const int e = tid;
        float acc[RS];
#pragma unroll
        for (int r = 0; r < RS; r++) acc[r] = 0.f;
        for (int c = 0; c < D_; c++) {
            float w = __ldg(&w_w[c * OUT_ + e]);
#pragma unroll
            for (int r = 0; r < RS; r++) acc[r] = fmaf(hsh[r][c], w, acc[r]);
        }
        const int hd = e >> 5;
        float s = 0.f;
#pragma unroll
        for (int r = 0; r < RS; r++) s = fmaf(efac[r][hd], acc[r], s);
        atomicAdd(&g_num[b * OUT_ + e], s);
        if (tid < NH_) {
            float d = 0.f;
#pragma unroll
            for (int r = 0; r < RS; r++) d += efac[r][tid];
            atomicAdd(&g_den[b * NH_ + tid], d);
        }
    }
}

// ---------------- K5: base term + Q_res + combine + normalize -------------
__global__ __launch_bounds__(256) void k5_final(
    const float* __restrict__ w_w,
    const float* __restrict__ res_w, const float* __restrict__ res_b,
    float* __restrict__ out)
{
    const int b = blockIdx.x;
    const int e = threadIdx.x;
    __shared__ float cs[D_];
    __shared__ float red[256];

    cs[e] = g_colsum[b * D_ + e];
    __syncthreads();

    float base = 0.f, qr = 0.f;
#pragma unroll 4
    for (int c = 0; c < D_; c++) {
        float x = cs[c];
        base = fmaf(x, __ldg(&w_w[c * OUT_ + e]), base);
        qr   = fmaf(x, __ldg(&res_w[c * OUT_ + e]), qr);
    }
    qr *= (1.0f / (float)M_);
    float Qres = fmaxf(qr + res_b[e], 0.f);
    float den = (float)M_ + g_den[b * NH_ + (e >> 5)];
    float ov = (base + g_num[b * OUT_ + e]) / den;
    float v = fmaxf(ov + Qres, 0.f);

    red[e] = v; __syncthreads();
    for (int s = 128; s > 0; s >>= 1) {
        if (e < s) red[e] += red[e + s];
        __syncthreads();
    }
    float mean = red[0] * (1.0f / 256.0f);
    __syncthreads();
    float dm = v - mean;
    red[e] = dm * dm; __syncthreads();
    for (int s = 128; s > 0; s >>= 1) {
        if (e < s) red[e] += red[e + s];
        __syncthreads();
    }
    float var = red[0] * (1.0f / 256.0f);
    out[b * OUT_ + e] = dm * rsqrtf(var + 1e-8f);
}

// ---------------- launch -----------------
extern "C" void kernel_launch(void* const* d_in, const int* in_sizes, int n_in,
                              void* d_out, int out_size)
{
    const float* h      = (const float*)d_in[0];
    const float* att_w  = (const float*)d_in[1];
    const float* att_b  = (const float*)d_in[2];
    const float* w_w    = (const float*)d_in[3];
    const float* res_w  = (const float*)d_in[4];
    const float* res_b  = (const float*)d_in[5];
    const float* gsl1_w = (const float*)d_in[6];
    const float* gsl1_b = (const float*)d_in[7];
    const float* gsl2_w = (const float*)d_in[8];
    const float* gsl2_b = (const float*)d_in[9];
    const int*   kptr   = (n_in > 10) ? (const int*)d_in[10] : nullptr;

    float* out  = (float*)d_out;              // [B, 1, OUT] -> 2048 floats
    float* mask = out + B_ * OUT_;            // [B, 1, M]   -> 400000 floats

    k0_zero<<<8, 256>>>();
    {
        dim3 grid((M_ + CHUNK - 1) / CHUNK, B_);   // 55 x 8 = 440 blocks, one wave @ 3 blocks/SM
        k1_gate<<<grid, 128>>>(h, gsl1_w, gsl1_b, gsl2_w, gsl2_b);
    }
    k2_select<<<B_, 1024>>>(kptr);
    {
        dim3 grid((M_ + 255) / 256, B_);
        k3_mask<<<grid, 256>>>(mask);
    }
    {
        dim3 grid(16, B_);
        k4_selected<<<grid, 256>>>(h, att_w, att_b, w_w);
    }
    k5_final<<<B_, 256>>>(w_w, res_w, res_b, out);
}